// round 14
// baseline (speedup 1.0000x reference)
#include <cuda_runtime.h>

// FMREDynamicDropout: out = x * bernoulli_mask(threefry2x32, keep_prob[c])
// x: [32, 384, 56, 56] fp32, feature_importance: [384] fp32
//
// JAX (threefry_partitionable) semantics, verified bit-exact since R2:
//   key(42) -> (0, 42); ks2 = 0 ^ 42 ^ 0x1BD11BDA = 0x1BD11BF0
//   per element i: hash counter words (0, i); bits[i] = o0 ^ o1
//   mask = bits < (ceil(keep[c] * 2^23) << 9)   (pure uint compare)
//
// R13: SINGLE-LAUNCH fusion. Evidence: the alu pipe (20 SHF + 21 LOP3/hash)
// is the measured floor of the hash body; R8 (95.4us kernel) already sits on
// it and every hash variant since regressed. The remaining measured slack is
// the prep launch: total-dur minus kernel-dur = 2.6-4.7us every round.
// Here each block computes the fi min/max itself (1.5 loads + ~12 ops +
// one barrier per thread, amortized over 2048 elements) and each thread
// derives its channel threshold with the byte-identical __f*_rn sequence.
// Hash body is VERBATIM R8 (best measured). One kernel, one graph node.

#define NCH   384
#define HW    3136u
#define NTOT  38535168u   // 32*384*56*56
#define KS2   0x1BD11BF0u

// threefry round: add as x1*ONE+x0 (ONE is a runtime param -> IMAD-friendly,
// ptxas balances), funnel-shift + xor on alu. Bit-exact since R2.
#define TFR(rot) do { x0 = x1 * ONE + x0;                              \
                      x1 = __funnelshift_l(x1, x1, (rot)) ^ x0; } while (0)

// returns o0 ^ o1 for counter words (0, i), key (0, 42)   [verbatim R8]
__device__ __forceinline__ unsigned tf_bits(unsigned i, unsigned ONE) {
    unsigned x1 = i * ONE + 42u;            // counter + ks1
    unsigned x0 = x1;                       // round-1 add: 0 + x1  (copy)
    x1 = __funnelshift_l(x1, x1, 13) ^ x0;  // round 1  (rot 13)
    TFR(15); TFR(26); TFR(6);               // rounds 2-4
    x0 = x0 * ONE + 42u;                    // inject: x0 += ks1
    x1 = x1 * ONE + (KS2 + 1u);             //         x1 += ks2 + 1
    TFR(17); TFR(29); TFR(16); TFR(24);     // rounds 5-8
    x0 = x0 * ONE + KS2;                    // inject: x0 += ks2
    x1 = x1 * ONE + 2u;                     //         x1 += ks0 + 2
    TFR(13); TFR(15); TFR(26); TFR(6);      // rounds 9-12
    x1 = x1 * ONE + 45u;                    // inject: x1 += ks1+3 (x0 += 0)
    TFR(17); TFR(29); TFR(16); TFR(24);     // rounds 13-16
    x0 = x0 * ONE + 42u;                    // inject: x0 += ks1
    x1 = x1 * ONE + (KS2 + 4u);             //         x1 += ks2 + 4
    TFR(13); TFR(15); TFR(26); TFR(6);      // rounds 17-20
    x0 = x0 * ONE + KS2;                    // final inject x0 += ks2
    x1 = x1 * ONE + 5u;                     //              x1 += ks0 + 5
    return x0 ^ x1;                         // output xor
}

// ---------------- fused kernel: per-block threshold prep + hash + select ----
__global__ void __launch_bounds__(256, 8)
drop_kernel(const float* __restrict__ x, const float* __restrict__ fi,
            float* __restrict__ out, unsigned ONE) {
    __shared__ float smn[8], smx[8];
    int tid = threadIdx.x;

    // ---- block-local min/max over fi[384] (every block, redundant, cheap) --
    // 256 threads: each loads fi[tid]; tid<128 additionally fi[tid+256].
    {
        float v0 = fi[tid];
        float v1 = (tid < 128) ? fi[tid + 256] : v0;
        float mn = fminf(v0, v1), mx = fmaxf(v0, v1);
        #pragma unroll
        for (int o = 16; o > 0; o >>= 1) {
            mn = fminf(mn, __shfl_xor_sync(0xffffffffu, mn, o));
            mx = fmaxf(mx, __shfl_xor_sync(0xffffffffu, mx, o));
        }
        if ((tid & 31) == 0) { smn[tid >> 5] = mn; smx[tid >> 5] = mx; }
    }
    __syncthreads();
    // all threads reduce the 8 per-warp partials (LDS broadcast, no 2nd bar)
    float fmin = smn[0], fmax = smx[0];
    #pragma unroll
    for (int i = 1; i < 8; i++) {
        fmin = fminf(fmin, smn[i]);
        fmax = fmaxf(fmax, smx[i]);
    }

    // ---- per-thread channel threshold (byte-identical fp sequence to prep) -
    unsigned j = (blockIdx.x * 256u + threadIdx.x) * 8u;   // j < NTOT, 8 | HW
    unsigned c = (j / HW) % (unsigned)NCH;                 // channel (8 share)
    float v = __ldg(&fi[c]);
    float scaled = __fdiv_rn(__fsub_rn(v, fmin), __fsub_rn(fmax, fmin));
    float rate   = __fadd_rn(0.1f, __fmul_rn(0.4f, __fsub_rn(1.0f, scaled)));
    float keep   = __fsub_rn(1.0f, rate);
    unsigned T = ((unsigned)ceilf(__fmul_rn(keep, 8388608.0f))) << 9;

    // ---- hash + select (verbatim R8 body) ----------------------------------
    float4 a = *reinterpret_cast<const float4*>(x + j);
    float4 b = *reinterpret_cast<const float4*>(x + j + 4);

    unsigned m[8];
    #pragma unroll
    for (int k = 0; k < 8; k++)
        m[k] = tf_bits(j + (unsigned)k, ONE);

    float4 oa, ob;
    oa.x = (m[0] < T) ? a.x : 0.0f;
    oa.y = (m[1] < T) ? a.y : 0.0f;
    oa.z = (m[2] < T) ? a.z : 0.0f;
    oa.w = (m[3] < T) ? a.w : 0.0f;
    ob.x = (m[4] < T) ? b.x : 0.0f;
    ob.y = (m[5] < T) ? b.y : 0.0f;
    ob.z = (m[6] < T) ? b.z : 0.0f;
    ob.w = (m[7] < T) ? b.w : 0.0f;

    *reinterpret_cast<float4*>(out + j)     = oa;
    *reinterpret_cast<float4*>(out + j + 4) = ob;
}

extern "C" void kernel_launch(void* const* d_in, const int* in_sizes, int n_in,
                              void* d_out, int out_size) {
    const float* x  = (const float*)d_in[0];
    const float* fi = (const float*)d_in[1];
    if (n_in >= 2 && in_sizes[0] == NCH) {   // robust to input ordering
        x  = (const float*)d_in[1];
        fi = (const float*)d_in[0];
    }
    // single fused launch: ONE = 1 at runtime (opaque add-steering hint)
    // NTOT / 8 elems-per-thread / 256 threads = 18816 blocks, no remainder
    drop_kernel<<<18816, 256>>>(x, fi, (float*)d_out, 1u);
}

// round 15
// speedup vs baseline: 1.0400x; 1.0400x over previous
#include <cuda_runtime.h>

// FMREDynamicDropout: out = x * bernoulli_mask(threefry2x32, keep_prob[c])
// x: [32, 384, 56, 56] fp32, feature_importance: [384] fp32
//
// JAX (threefry_partitionable) semantics, verified bit-exact since R2:
//   key(42) -> (0, 42); ks2 = 0 ^ 42 ^ 0x1BD11BDA = 0x1BD11BF0
//   per element i: hash counter words (0, i); bits[i] = o0 ^ o1
//   mask = bits < (ceil(keep[c] * 2^23) << 9)   (pure uint compare)
//
// R14: single launch with AMORTIZED prep. R13's fused version cost +11us
// because every thread ran the threshold math incl. a full __fdiv_rn.
// Here: warp 0 alone reduces fi[384]; lane 0 alone computes the (<=2)
// channel thresholds this block can touch (block = 2048 consecutive elems
// < HW=3136, so it spans at most one channel boundary); everyone else waits
// at one barrier (BAR-parked warps don't consume issue slots; 8 CTAs/SM
// keep the pipes fed). Per-thread threshold fetch becomes ISETP + LDS,
// cheaper than R8's div/mod + LDG. Hash body is VERBATIM R8 (95.4us, the
// measured alu-pipe floor: 20 SHF + 21 LOP3 per hash).

#define NCH   384
#define HW    3136u
#define NTOT  38535168u   // 32*384*56*56
#define KS2   0x1BD11BF0u

// threefry round: add as x1*ONE+x0 (ONE is a runtime param; ptxas balances
// IMAD<->IADD3), funnel-shift + xor on alu. Bit-exact since R2.
#define TFR(rot) do { x0 = x1 * ONE + x0;                              \
                      x1 = __funnelshift_l(x1, x1, (rot)) ^ x0; } while (0)

// returns o0 ^ o1 for counter words (0, i), key (0, 42)   [verbatim R8]
__device__ __forceinline__ unsigned tf_bits(unsigned i, unsigned ONE) {
    unsigned x1 = i * ONE + 42u;            // counter + ks1
    unsigned x0 = x1;                       // round-1 add: 0 + x1  (copy)
    x1 = __funnelshift_l(x1, x1, 13) ^ x0;  // round 1  (rot 13)
    TFR(15); TFR(26); TFR(6);               // rounds 2-4
    x0 = x0 * ONE + 42u;                    // inject: x0 += ks1
    x1 = x1 * ONE + (KS2 + 1u);             //         x1 += ks2 + 1
    TFR(17); TFR(29); TFR(16); TFR(24);     // rounds 5-8
    x0 = x0 * ONE + KS2;                    // inject: x0 += ks2
    x1 = x1 * ONE + 2u;                     //         x1 += ks0 + 2
    TFR(13); TFR(15); TFR(26); TFR(6);      // rounds 9-12
    x1 = x1 * ONE + 45u;                    // inject: x1 += ks1+3 (x0 += 0)
    TFR(17); TFR(29); TFR(16); TFR(24);     // rounds 13-16
    x0 = x0 * ONE + 42u;                    // inject: x0 += ks1
    x1 = x1 * ONE + (KS2 + 4u);             //         x1 += ks2 + 4
    TFR(13); TFR(15); TFR(26); TFR(6);      // rounds 17-20
    x0 = x0 * ONE + KS2;                    // final inject x0 += ks2
    x1 = x1 * ONE + 5u;                     //              x1 += ks0 + 5
    return x0 ^ x1;                         // output xor
}

// threshold for one channel value, byte-identical fp sequence to reference
__device__ __forceinline__ unsigned chan_thresh(float v, float fmin, float fmax) {
    float scaled = __fdiv_rn(__fsub_rn(v, fmin), __fsub_rn(fmax, fmin));
    float rate   = __fadd_rn(0.1f, __fmul_rn(0.4f, __fsub_rn(1.0f, scaled)));
    float keep   = __fsub_rn(1.0f, rate);
    return ((unsigned)ceilf(__fmul_rn(keep, 8388608.0f))) << 9;   // <= 0.9*2^23
}

// ---------------- fused kernel ----------------------------------------------
__global__ void __launch_bounds__(256)
drop_kernel(const float* __restrict__ x, const float* __restrict__ fi,
            float* __restrict__ out, unsigned ONE) {
    __shared__ unsigned sT[2];      // thresholds for the block's two channels
    __shared__ unsigned sBound;     // first element index of the second channel
    int tid = threadIdx.x;

    // ---- warp 0 only: full min/max over fi[384] + both channel thresholds --
    if (tid < 32) {
        float v = fi[tid];
        float mn = v, mx = v;
        #pragma unroll
        for (int k = 1; k < 12; k++) {          // 384 = 32 * 12
            float u = fi[tid + k * 32];
            mn = fminf(mn, u); mx = fmaxf(mx, u);
        }
        #pragma unroll
        for (int o = 16; o > 0; o >>= 1) {
            mn = fminf(mn, __shfl_xor_sync(0xffffffffu, mn, o));
            mx = fmaxf(mx, __shfl_xor_sync(0xffffffffu, mx, o));
        }
        if (tid == 0) {
            unsigned q  = (blockIdx.x * 2048u) / HW;   // channel-slice index
            unsigned c0 = q % (unsigned)NCH;
            unsigned c1 = (q + 1u) % (unsigned)NCH;    // next slice (may wrap)
            sBound = (q + 1u) * HW;                    // first j of next slice
            sT[0] = chan_thresh(fi[c0], mn, mx);
            sT[1] = chan_thresh(fi[c1], mn, mx);
        }
    }
    __syncthreads();

    // ---- per-thread: pick threshold by boundary compare (ISETP + LDS) ------
    unsigned j = (blockIdx.x * 256u + tid) * 8u;       // j < NTOT, 8 | HW
    unsigned T = sT[j >= sBound];                      // block spans <= 2 chans

    // ---- hash + select (verbatim R8 body) ----------------------------------
    float4 a = *reinterpret_cast<const float4*>(x + j);
    float4 b = *reinterpret_cast<const float4*>(x + j + 4);

    unsigned m[8];
    #pragma unroll
    for (int k = 0; k < 8; k++)
        m[k] = tf_bits(j + (unsigned)k, ONE);

    float4 oa, ob;
    oa.x = (m[0] < T) ? a.x : 0.0f;
    oa.y = (m[1] < T) ? a.y : 0.0f;
    oa.z = (m[2] < T) ? a.z : 0.0f;
    oa.w = (m[3] < T) ? a.w : 0.0f;
    ob.x = (m[4] < T) ? b.x : 0.0f;
    ob.y = (m[5] < T) ? b.y : 0.0f;
    ob.z = (m[6] < T) ? b.z : 0.0f;
    ob.w = (m[7] < T) ? b.w : 0.0f;

    *reinterpret_cast<float4*>(out + j)     = oa;
    *reinterpret_cast<float4*>(out + j + 4) = ob;
}

extern "C" void kernel_launch(void* const* d_in, const int* in_sizes, int n_in,
                              void* d_out, int out_size) {
    const float* x  = (const float*)d_in[0];
    const float* fi = (const float*)d_in[1];
    if (n_in >= 2 && in_sizes[0] == NCH) {   // robust to input ordering
        x  = (const float*)d_in[1];
        fi = (const float*)d_in[0];
    }
    // single fused launch; ONE = 1 at runtime (opaque add-steering hint)
    // NTOT / 8 elems-per-thread / 256 threads = 18816 blocks, no remainder
    drop_kernel<<<18816, 256>>>(x, fi, (float*)d_out, 1u);
}

// round 16
// speedup vs baseline: 1.0407x; 1.0006x over previous
#include <cuda_runtime.h>

// FMREDynamicDropout: out = x * bernoulli_mask(threefry2x32, keep_prob[c])
// x: [32, 384, 56, 56] fp32, feature_importance: [384] fp32
//
// JAX (threefry_partitionable) semantics, verified bit-exact since R2:
//   key(42) -> (0, 42); ks2 = 0 ^ 42 ^ 0x1BD11BDA = 0x1BD11BF0
//   per element i: hash counter words (0, i); bits[i] = o0 ^ o1
//   mask = bits < (ceil(keep[c] * 2^23) << 9)   (pure uint compare)
//
// R15: fused single launch with LATE barrier. R14 (early barrier) parked
// every warp for warp0's full prep latency (~800cyc incl 12 LDGs + FDIV)
// before any hash work existed -> +7us. Here the barrier moves AFTER the
// hash: all warps issue x-loads, warp0 runs prep, everyone (incl warp0)
// hashes, THEN syncs and reads the threshold from smem. Parked warps have
// already done their work; warp0 fills its own lag with dense hash instrs;
// other resident CTAs fill the rest. Hash/select body is VERBATIM R8
// (95.4us kernel, the measured alu-pipe floor). Single graph node keeps
// the total-kernel gap at ~1.5-1.9us (vs 2.6-4.7 for two launches).

#define NCH   384
#define HW    3136u
#define NTOT  38535168u   // 32*384*56*56
#define KS2   0x1BD11BF0u

// threefry round: add as x1*ONE+x0 (ONE is a runtime param; ptxas balances
// IMAD<->IADD3), funnel-shift + xor on alu. Bit-exact since R2.
#define TFR(rot) do { x0 = x1 * ONE + x0;                              \
                      x1 = __funnelshift_l(x1, x1, (rot)) ^ x0; } while (0)

// returns o0 ^ o1 for counter words (0, i), key (0, 42)   [verbatim R8]
__device__ __forceinline__ unsigned tf_bits(unsigned i, unsigned ONE) {
    unsigned x1 = i * ONE + 42u;            // counter + ks1
    unsigned x0 = x1;                       // round-1 add: 0 + x1  (copy)
    x1 = __funnelshift_l(x1, x1, 13) ^ x0;  // round 1  (rot 13)
    TFR(15); TFR(26); TFR(6);               // rounds 2-4
    x0 = x0 * ONE + 42u;                    // inject: x0 += ks1
    x1 = x1 * ONE + (KS2 + 1u);             //         x1 += ks2 + 1
    TFR(17); TFR(29); TFR(16); TFR(24);     // rounds 5-8
    x0 = x0 * ONE + KS2;                    // inject: x0 += ks2
    x1 = x1 * ONE + 2u;                     //         x1 += ks0 + 2
    TFR(13); TFR(15); TFR(26); TFR(6);      // rounds 9-12
    x1 = x1 * ONE + 45u;                    // inject: x1 += ks1+3 (x0 += 0)
    TFR(17); TFR(29); TFR(16); TFR(24);     // rounds 13-16
    x0 = x0 * ONE + 42u;                    // inject: x0 += ks1
    x1 = x1 * ONE + (KS2 + 4u);             //         x1 += ks2 + 4
    TFR(13); TFR(15); TFR(26); TFR(6);      // rounds 17-20
    x0 = x0 * ONE + KS2;                    // final inject x0 += ks2
    x1 = x1 * ONE + 5u;                     //              x1 += ks0 + 5
    return x0 ^ x1;                         // output xor
}

// threshold for one channel value, byte-identical fp sequence to reference
__device__ __forceinline__ unsigned chan_thresh(float v, float fmin, float fmax) {
    float scaled = __fdiv_rn(__fsub_rn(v, fmin), __fsub_rn(fmax, fmin));
    float rate   = __fadd_rn(0.1f, __fmul_rn(0.4f, __fsub_rn(1.0f, scaled)));
    float keep   = __fsub_rn(1.0f, rate);
    return ((unsigned)ceilf(__fmul_rn(keep, 8388608.0f))) << 9;   // <= 0.9*2^23
}

// ---------------- fused kernel: loads -> warp0 prep -> hash -> bar -> select -
__global__ void __launch_bounds__(256)
drop_kernel(const float* __restrict__ x, const float* __restrict__ fi,
            float* __restrict__ out, unsigned ONE) {
    __shared__ unsigned sT[2];      // thresholds for the block's two channels
    __shared__ unsigned sBound;     // first element index of the second channel
    int tid = threadIdx.x;

    // ---- 1. everyone issues their x loads first (independent of prep) ------
    unsigned j = (blockIdx.x * 256u + tid) * 8u;       // j < NTOT, 8 | HW
    float4 a = *reinterpret_cast<const float4*>(x + j);
    float4 b = *reinterpret_cast<const float4*>(x + j + 4);

    // ---- 2. warp 0 only: fi[384] min/max + this block's <=2 thresholds -----
    if (tid < 32) {
        float v = fi[tid];
        float mn = v, mx = v;
        #pragma unroll
        for (int k = 1; k < 12; k++) {          // 384 = 32 * 12, coalesced
            float u = fi[tid + k * 32];
            mn = fminf(mn, u); mx = fmaxf(mx, u);
        }
        #pragma unroll
        for (int o = 16; o > 0; o >>= 1) {
            mn = fminf(mn, __shfl_xor_sync(0xffffffffu, mn, o));
            mx = fmaxf(mx, __shfl_xor_sync(0xffffffffu, mx, o));
        }
        if (tid == 0) {
            unsigned q  = (blockIdx.x * 2048u) / HW;   // channel-slice index
            unsigned c0 = q % (unsigned)NCH;
            unsigned c1 = (q + 1u) % (unsigned)NCH;    // next slice (may wrap)
            sBound = (q + 1u) * HW;                    // first j of next slice
            sT[0] = chan_thresh(fi[c0], mn, mx);
            sT[1] = chan_thresh(fi[c1], mn, mx);
        }
    }

    // ---- 3. hash (verbatim R8; warp0 does this right after its prep) -------
    unsigned m[8];
    #pragma unroll
    for (int k = 0; k < 8; k++)
        m[k] = tf_bits(j + (unsigned)k, ONE);

    // ---- 4. barrier AFTER the heavy work ------------------------------------
    __syncthreads();

    // ---- 5. threshold fetch (ISETP + LDS) + select + store ------------------
    unsigned T = sT[j >= sBound];                      // block spans <= 2 chans

    float4 oa, ob;
    oa.x = (m[0] < T) ? a.x : 0.0f;
    oa.y = (m[1] < T) ? a.y : 0.0f;
    oa.z = (m[2] < T) ? a.z : 0.0f;
    oa.w = (m[3] < T) ? a.w : 0.0f;
    ob.x = (m[4] < T) ? b.x : 0.0f;
    ob.y = (m[5] < T) ? b.y : 0.0f;
    ob.z = (m[6] < T) ? b.z : 0.0f;
    ob.w = (m[7] < T) ? b.w : 0.0f;

    *reinterpret_cast<float4*>(out + j)     = oa;
    *reinterpret_cast<float4*>(out + j + 4) = ob;
}

extern "C" void kernel_launch(void* const* d_in, const int* in_sizes, int n_in,
                              void* d_out, int out_size) {
    const float* x  = (const float*)d_in[0];
    const float* fi = (const float*)d_in[1];
    if (n_in >= 2 && in_sizes[0] == NCH) {   // robust to input ordering
        x  = (const float*)d_in[1];
        fi = (const float*)d_in[0];
    }
    // single fused launch; ONE = 1 at runtime (opaque add-steering hint)
    // NTOT / 8 elems-per-thread / 256 threads = 18816 blocks, no remainder
    drop_kernel<<<18816, 256>>>(x, fi, (float*)d_out, 1u);
}